// round 4
// baseline (speedup 1.0000x reference)
#include <cuda_runtime.h>
#include <cuda_bf16.h>
#include <math.h>

#define NN 50000
#define EE 800000
#define NODE_IN 128
#define HID 256
#define OUT_D 256
#define EDGE_DIM 16
#define HEADS 4
#define CH 64

// ---------------- scratch (static device globals) ---------------------------
__device__ float g_xcat[(size_t)NN * 512];
__device__ float g_xh[(size_t)NN * 256];
__device__ float g_h[(size_t)NN * 256];
__device__ int   g_cnt[NN];
__device__ int   g_off[NN + 1];
__device__ int   g_cur[NN];
__device__ int   g_csr[EE];     // src node per CSR slot
__device__ int   g_eid[EE];     // edge id per CSR slot
__device__ float g_asrc[NN * HEADS];
__device__ float g_adst[NN * HEADS];
__device__ int   g_src[EE];
__device__ int   g_dst[EE];
__device__ int   g_is64;

// ---------------- helpers ---------------------------------------------------
__device__ __forceinline__ float lrelu(float x) { return x > 0.f ? x : 0.2f * x; }
__device__ __forceinline__ float elu(float x)   { return x > 0.f ? x : expf(x) - 1.f; }
__device__ __forceinline__ float wredmax(float v) {
    #pragma unroll
    for (int o = 16; o; o >>= 1) v = fmaxf(v, __shfl_xor_sync(0xffffffffu, v, o));
    return v;
}
__device__ __forceinline__ float wredsum(float v) {
    #pragma unroll
    for (int o = 16; o; o >>= 1) v += __shfl_xor_sync(0xffffffffu, v, o);
    return v;
}

// ---------------- edge index normalization ---------------------------------
__global__ void detect_kernel(const int* __restrict__ ei_raw) {
    if (threadIdx.x == 0) {
        int any = 0;
        #pragma unroll 1
        for (int i = 1; i < 256; i += 2) any |= ei_raw[i];
        g_is64 = (any == 0) ? 1 : 0;
    }
}

__global__ void convert_edges(const int* __restrict__ ei_raw) {
    int e = blockIdx.x * blockDim.x + threadIdx.x;
    if (e >= EE) return;
    int s, d;
    if (g_is64) {
        s = ei_raw[2 * (size_t)e];
        d = ei_raw[2 * ((size_t)EE + e)];
    } else {
        s = ei_raw[e];
        d = ei_raw[EE + e];
    }
    g_src[e] = min(max(s, 0), NN - 1);
    g_dst[e] = min(max(d, 0), NN - 1);
}

// ---------------- graph build -----------------------------------------------
__global__ void zero_cnt() {
    int i = blockIdx.x * blockDim.x + threadIdx.x;
    if (i < NN) g_cnt[i] = 0;
}

__global__ void edge_count() {
    int e = blockIdx.x * blockDim.x + threadIdx.x;
    if (e >= EE) return;
    atomicAdd(&g_cnt[g_dst[e]], 1);
}

__global__ void prefix_kernel() {
    __shared__ int sh[1024];
    const int CHK = (NN + 1023) / 1024;  // 49
    int t = threadIdx.x;
    int start = t * CHK;
    int stop = min(start + CHK, NN);
    int s = 0;
    for (int i = start; i < stop; i++) s += g_cnt[i];
    sh[t] = s;
    __syncthreads();
    #pragma unroll
    for (int off = 1; off < 1024; off <<= 1) {
        int v = (t >= off) ? sh[t - off] : 0;
        __syncthreads();
        sh[t] += v;
        __syncthreads();
    }
    int run = sh[t] - s;
    for (int i = start; i < stop; i++) {
        g_off[i] = run;
        g_cur[i] = run;
        run += g_cnt[i];
    }
    if (t == 1023) g_off[NN] = sh[1023];
}

__global__ void edge_fill_csr() {
    int e = blockIdx.x * blockDim.x + threadIdx.x;
    if (e >= EE) return;
    int pos = atomicAdd(&g_cur[g_dst[e]], 1);
    g_csr[pos] = g_src[e];
    g_eid[pos] = e;
}

// ---------------- GEMM: C[M,256] = A[M,K] @ W[K,256] (+bias) ----------------
// 128x128 block, BK=8, 256 threads, 8x8/thread (split 4+4), double-buffered.
__global__ void __launch_bounds__(256, 2)
gemm128(const float* __restrict__ A, int lda,
        const float* __restrict__ W,
        const float* __restrict__ bias,
        float* __restrict__ C, int ldc,
        int M, int K) {
    __shared__ float As[2][8][132];
    __shared__ float Bs[2][8][132];
    int bm = blockIdx.y * 128;
    int bn = blockIdx.x * 128;
    int tid = threadIdx.x;
    int tx = tid & 15, ty = tid >> 4;

    float acc[8][8];
    #pragma unroll
    for (int i = 0; i < 8; i++)
        #pragma unroll
        for (int j = 0; j < 8; j++) acc[i][j] = 0.f;

    // A load: row = tid>>1 (0..127), col = (tid&1)*4
    int ar = tid >> 1;
    int ac = (tid & 1) * 4;
    int grA = bm + ar;
    bool aok = grA < M;
    const float* Aptr = A + (size_t)grA * lda + ac;
    // W load: row = tid>>5 (0..7), col = (tid&31)*4
    int wr = tid >> 5;
    int wc = (tid & 31) * 4;
    const float* Wptr = W + (size_t)wr * 256 + bn + wc;

    float4 av = aok ? *(const float4*)Aptr : make_float4(0.f, 0.f, 0.f, 0.f);
    float4 wv = *(const float4*)Wptr;

    As[0][ac + 0][ar] = av.x;
    As[0][ac + 1][ar] = av.y;
    As[0][ac + 2][ar] = av.z;
    As[0][ac + 3][ar] = av.w;
    *(float4*)&Bs[0][wr][wc] = wv;
    __syncthreads();

    int ntiles = K >> 3;
    int buf = 0;
    for (int t = 0; t < ntiles; t++) {
        bool has_next = (t + 1 < ntiles);
        if (has_next) {
            av = aok ? *(const float4*)(Aptr + (t + 1) * 8) : make_float4(0.f, 0.f, 0.f, 0.f);
            wv = *(const float4*)(Wptr + (size_t)(t + 1) * 8 * 256);
        }
        #pragma unroll
        for (int kk = 0; kk < 8; kk++) {
            float4 a0 = *(const float4*)&As[buf][kk][ty * 4];
            float4 a1 = *(const float4*)&As[buf][kk][ty * 4 + 64];
            float4 b0 = *(const float4*)&Bs[buf][kk][tx * 4];
            float4 b1 = *(const float4*)&Bs[buf][kk][tx * 4 + 64];
            float a[8] = {a0.x, a0.y, a0.z, a0.w, a1.x, a1.y, a1.z, a1.w};
            float b[8] = {b0.x, b0.y, b0.z, b0.w, b1.x, b1.y, b1.z, b1.w};
            #pragma unroll
            for (int i = 0; i < 8; i++)
                #pragma unroll
                for (int j = 0; j < 8; j++) acc[i][j] += a[i] * b[j];
        }
        if (has_next) {
            int nb = buf ^ 1;
            As[nb][ac + 0][ar] = av.x;
            As[nb][ac + 1][ar] = av.y;
            As[nb][ac + 2][ar] = av.z;
            As[nb][ac + 3][ar] = av.w;
            *(float4*)&Bs[nb][wr][wc] = wv;
            __syncthreads();
            buf = nb;
        }
    }

    // epilogue: rows {bm + ii*64 + ty*4 + i}, cols {bn + jj*64 + tx*4 + j}
    #pragma unroll
    for (int ii = 0; ii < 2; ii++) {
        #pragma unroll
        for (int i = 0; i < 4; i++) {
            int r = bm + ii * 64 + ty * 4 + i;
            if (r >= M) continue;
            #pragma unroll
            for (int jj = 0; jj < 2; jj++) {
                int c = bn + jj * 64 + tx * 4;
                float4 o;
                float* ap = &acc[ii * 4 + i][jj * 4];
                if (bias) {
                    o.x = ap[0] + bias[c + 0];
                    o.y = ap[1] + bias[c + 1];
                    o.z = ap[2] + bias[c + 2];
                    o.w = ap[3] + bias[c + 3];
                } else {
                    o.x = ap[0]; o.y = ap[1]; o.z = ap[2]; o.w = ap[3];
                }
                *(float4*)(C + (size_t)r * ldc + c) = o;
            }
        }
    }
}

// ---------------- edge mean (CSR gather) + edge_proj ------------------------
// 16 nodes per block, 256 threads.
__global__ void edgeproj_kernel(const float* __restrict__ eattr,
                                const float* __restrict__ Wep,
                                const float* __restrict__ bep) {
    __shared__ float sW[EDGE_DIM][256];
    __shared__ float snef[16][EDGE_DIM];
    int tid = threadIdx.x;
    for (int i = tid; i < EDGE_DIM * 256; i += 256)
        sW[i >> 8][i & 255] = Wep[i];

    int g = tid >> 4;       // node within block group (0..15)
    int j = tid & 15;       // edge-dim lane
    int n = blockIdx.x * 16 + g;

    float s = 0.f;
    int deg = 0;
    if (n < NN) {
        int off = g_off[n];
        deg = g_off[n + 1] - off;
        for (int e = 0; e < deg; e++) {
            int eid = g_eid[off + e];
            s += eattr[(size_t)eid * EDGE_DIM + j];
        }
    }
    snef[g][j] = s / fmaxf((float)deg, 1.0f);
    __syncthreads();

    // each thread: node g, 16 output cols starting at (tid&15)*16
    if (n < NN) {
        int c0 = j * 16;
        float acc[16];
        #pragma unroll
        for (int c = 0; c < 16; c++) acc[c] = bep[c0 + c];
        #pragma unroll
        for (int k = 0; k < EDGE_DIM; k++) {
            float v = snef[g][k];
            #pragma unroll
            for (int c = 0; c < 16; c++) acc[c] += v * sW[k][c0 + c];
        }
        float* outp = g_xcat + (size_t)n * 512 + 256 + c0;
        #pragma unroll
        for (int c = 0; c < 16; c += 4)
            *(float4*)(outp + c) = make_float4(acc[c], acc[c + 1], acc[c + 2], acc[c + 3]);
    }
}

// ---------------- attention dot products ------------------------------------
__global__ void attn_dots(const float* __restrict__ as_p,
                          const float* __restrict__ ad_p) {
    int n = blockIdx.x;
    int h = threadIdx.x >> 5;
    int l = threadIdx.x & 31;
    const float* row = g_xh + (size_t)n * 256 + h * CH;
    float x0 = row[l], x1 = row[l + 32];
    float s = x0 * as_p[h * CH + l] + x1 * as_p[h * CH + l + 32];
    float d = x0 * ad_p[h * CH + l] + x1 * ad_p[h * CH + l + 32];
    s = wredsum(s);
    d = wredsum(d);
    if (l == 0) {
        g_asrc[n * HEADS + h] = s;
        g_adst[n * HEADS + h] = d;
    }
}

// ---------------- GAT aggregation (max pass + fused denom/gather pass) ------
__global__ void gat_aggregate(const float* __restrict__ bias,
                              float* __restrict__ out) {
    int n = blockIdx.x;
    int h = threadIdx.x >> 5;
    int l = threadIdx.x & 31;
    int off = g_off[n];
    int deg = g_off[n + 1] - off;
    float adst = g_adst[n * HEADS + h];
    float slf = lrelu(g_asrc[n * HEADS + h] + adst);

    // pass 1: max (lane-parallel)
    float m = slf;
    for (int e = l; e < deg; e += 32) {
        int s = g_csr[off + e];
        m = fmaxf(m, lrelu(g_asrc[s * HEADS + h] + adst));
    }
    m = wredmax(m);

    // pass 2: fused denom + weighted gather.
    // Lane-parallel w for 32 edges, then shuffle-broadcast; lane = channel.
    float ds = 0.f;
    float a0 = 0.f, a1 = 0.f;
    for (int base = 0; base < deg; base += 32) {
        int e = base + l;
        int s = 0;
        float w = 0.f;
        if (e < deg) {
            s = g_csr[off + e];
            w = expf(lrelu(g_asrc[s * HEADS + h] + adst) - m);
            ds += w;
        }
        int cnt = min(deg - base, 32);
        for (int jj = 0; jj < cnt; jj++) {
            float wj = __shfl_sync(0xffffffffu, w, jj);
            int sj = __shfl_sync(0xffffffffu, s, jj);
            const float* r = g_xh + (size_t)sj * 256 + h * CH;
            a0 += wj * r[l];
            a1 += wj * r[l + 32];
        }
    }
    float wslf = expf(slf - m);
    ds = wredsum(ds) + wslf;
    float inv = 1.0f / ds;

    const float* xr = g_xh + (size_t)n * 256 + h * CH;
    a0 = (a0 + wslf * xr[l]) * inv;
    a1 = (a1 + wslf * xr[l + 32]) * inv;

    float b0 = bias[h * CH + l];
    float b1 = bias[h * CH + l + 32];
    out[(size_t)n * 256 + h * CH + l]      = elu(a0 + b0);
    out[(size_t)n * 256 + h * CH + l + 32] = elu(a1 + b1);
}

// ---------------- launch ----------------------------------------------------
extern "C" void kernel_launch(void* const* d_in, const int* in_sizes, int n_in,
                              void* d_out, int out_size) {
    const float* node_feats = (const float*)d_in[0];
    const float* edge_attr  = (const float*)d_in[1];
    const float* Wnp = (const float*)d_in[2];
    const float* bnp = (const float*)d_in[3];
    const float* Wep = (const float*)d_in[4];
    const float* bep = (const float*)d_in[5];
    const float* Wg1 = (const float*)d_in[6];
    const float* as1 = (const float*)d_in[7];
    const float* ad1 = (const float*)d_in[8];
    const float* bg1 = (const float*)d_in[9];
    const float* Wg2 = (const float*)d_in[10];
    const float* as2 = (const float*)d_in[11];
    const float* ad2 = (const float*)d_in[12];
    const float* bg2 = (const float*)d_in[13];
    const float* Wo  = (const float*)d_in[14];
    const float* bo  = (const float*)d_in[15];
    const int* ei_raw = (const int*)d_in[16];
    float* out = (float*)d_out;

    float* xcat; cudaGetSymbolAddress((void**)&xcat, g_xcat);
    float* xh;   cudaGetSymbolAddress((void**)&xh,   g_xh);
    float* hbuf; cudaGetSymbolAddress((void**)&hbuf, g_h);

    const int EB = (EE + 255) / 256;

    detect_kernel<<<1, 32>>>(ei_raw);
    convert_edges<<<EB, 256>>>(ei_raw);

    zero_cnt<<<(NN + 255) / 256, 256>>>();
    edge_count<<<EB, 256>>>();
    prefix_kernel<<<1, 1024>>>();
    edge_fill_csr<<<EB, 256>>>();

    dim3 ggrid(2, (NN + 127) / 128);  // 256 cols / 128, M tiles

    // node_proj -> xcat[:, :256]
    gemm128<<<ggrid, 256>>>(node_feats, NODE_IN, Wnp, bnp, xcat, 512, NN, NODE_IN);
    // edge mean + edge_proj -> xcat[:, 256:512]
    edgeproj_kernel<<<(NN + 15) / 16, 256>>>(edge_attr, Wep, bep);

    // ---- GAT layer 1 ----
    gemm128<<<ggrid, 256>>>(xcat, 512, Wg1, nullptr, xh, 256, NN, 512);
    attn_dots<<<NN, 128>>>(as1, ad1);
    gat_aggregate<<<NN, 128>>>(bg1, hbuf);

    // ---- GAT layer 2 ----
    gemm128<<<ggrid, 256>>>(hbuf, 256, Wg2, nullptr, xh, 256, NN, 256);
    attn_dots<<<NN, 128>>>(as2, ad2);
    gat_aggregate<<<NN, 128>>>(bg2, hbuf);

    // ---- out_proj -> d_out ----
    gemm128<<<ggrid, 256>>>(hbuf, 256, Wo, bo, out, 256, NN, 256);
}

// round 6
// speedup vs baseline: 1.9351x; 1.9351x over previous
#include <cuda_runtime.h>
#include <cuda_bf16.h>
#include <math.h>

#define NN 50000
#define EE 800000
#define NODE_IN 128
#define HID 256
#define OUT_D 256
#define EDGE_DIM 16
#define HEADS 4
#define CH 64

// ---------------- scratch (static device globals) ---------------------------
__device__ float g_xcat[(size_t)NN * 512];
__device__ float g_xh[(size_t)NN * 256];
__device__ float g_h[(size_t)NN * 256];
__device__ int   g_cnt[NN];
__device__ int   g_off[NN + 1];
__device__ int   g_cur[NN];
__device__ int   g_csr[EE];     // src node per CSR slot
__device__ int   g_eid[EE];     // edge id per CSR slot
__device__ float g_asrc[NN * HEADS];
__device__ float g_adst[NN * HEADS];
__device__ int   g_src[EE];
__device__ int   g_dst[EE];
__device__ int   g_is64;

// ---------------- helpers ---------------------------------------------------
__device__ __forceinline__ float lrelu(float x) { return x > 0.f ? x : 0.2f * x; }
__device__ __forceinline__ float elu(float x)   { return x > 0.f ? x : expf(x) - 1.f; }
__device__ __forceinline__ float wredmax(float v) {
    #pragma unroll
    for (int o = 16; o; o >>= 1) v = fmaxf(v, __shfl_xor_sync(0xffffffffu, v, o));
    return v;
}
__device__ __forceinline__ float wredsum(float v) {
    #pragma unroll
    for (int o = 16; o; o >>= 1) v += __shfl_xor_sync(0xffffffffu, v, o);
    return v;
}
__device__ __forceinline__ unsigned f2tf32(float x) {
    unsigned u;
    asm("cvt.rna.tf32.f32 %0, %1;" : "=r"(u) : "f"(x));
    return u;
}

// ---------------- edge index normalization ---------------------------------
__global__ void detect_kernel(const int* __restrict__ ei_raw) {
    if (threadIdx.x == 0) {
        int any = 0;
        #pragma unroll 1
        for (int i = 1; i < 256; i += 2) any |= ei_raw[i];
        g_is64 = (any == 0) ? 1 : 0;
    }
}

__global__ void convert_edges(const int* __restrict__ ei_raw) {
    int e = blockIdx.x * blockDim.x + threadIdx.x;
    if (e >= EE) return;
    int s, d;
    if (g_is64) {
        s = ei_raw[2 * (size_t)e];
        d = ei_raw[2 * ((size_t)EE + e)];
    } else {
        s = ei_raw[e];
        d = ei_raw[EE + e];
    }
    g_src[e] = min(max(s, 0), NN - 1);
    g_dst[e] = min(max(d, 0), NN - 1);
}

// ---------------- graph build -----------------------------------------------
__global__ void zero_cnt() {
    int i = blockIdx.x * blockDim.x + threadIdx.x;
    if (i < NN) g_cnt[i] = 0;
}

__global__ void edge_count() {
    int e = blockIdx.x * blockDim.x + threadIdx.x;
    if (e >= EE) return;
    atomicAdd(&g_cnt[g_dst[e]], 1);
}

__global__ void prefix_kernel() {
    __shared__ int sh[1024];
    const int CHK = (NN + 1023) / 1024;  // 49
    int t = threadIdx.x;
    int start = t * CHK;
    int stop = min(start + CHK, NN);
    int s = 0;
    for (int i = start; i < stop; i++) s += g_cnt[i];
    sh[t] = s;
    __syncthreads();
    #pragma unroll
    for (int off = 1; off < 1024; off <<= 1) {
        int v = (t >= off) ? sh[t - off] : 0;
        __syncthreads();
        sh[t] += v;
        __syncthreads();
    }
    int run = sh[t] - s;
    for (int i = start; i < stop; i++) {
        g_off[i] = run;
        g_cur[i] = run;
        run += g_cnt[i];
    }
    if (t == 1023) g_off[NN] = sh[1023];
}

__global__ void edge_fill_csr() {
    int e = blockIdx.x * blockDim.x + threadIdx.x;
    if (e >= EE) return;
    int pos = atomicAdd(&g_cur[g_dst[e]], 1);
    g_csr[pos] = g_src[e];
    g_eid[pos] = e;
}

// ---------------- tf32 tensor-core GEMM -------------------------------------
// C[M,256] = A[M,K] @ W[K,256] (+bias). BM=128, BN=128, BK=32.
// 256 threads = 8 warps (2m x 4n); warp tile 64x32 = 4x4 mma tiles of m16n8k8.
// As stride 36 / Bs stride 136 -> conflict-free fragment LDS.
__global__ void __launch_bounds__(256, 2)
gemm_tf32(const float* __restrict__ A, int lda,
          const float* __restrict__ W,
          const float* __restrict__ bias,
          float* __restrict__ C, int ldc,
          int M, int K) {
    __shared__ float As[128][36];
    __shared__ float Bs[32][136];

    int bm = blockIdx.y * 128;
    int bn = blockIdx.x * 128;
    int tid = threadIdx.x;
    int wid = tid >> 5;
    int lane = tid & 31;
    int gid = lane >> 2;     // group id 0..7
    int tig = lane & 3;      // thread-in-group 0..3
    int warp_m = (wid & 1) * 64;
    int warp_n = (wid >> 1) * 32;

    float c[4][4][4];
    #pragma unroll
    for (int i = 0; i < 4; i++)
        #pragma unroll
        for (int j = 0; j < 4; j++)
            #pragma unroll
            for (int r = 0; r < 4; r++) c[i][j][r] = 0.f;

    // gmem load mapping
    int ar = tid >> 1;               // 0..127
    int ac = (tid & 1) * 16;         // 0 or 16
    bool aok = (bm + ar) < M;
    const float* Aptr = A + (size_t)(bm + ar) * lda + ac;
    int br = tid >> 3;               // 0..31
    int bc = (tid & 7) * 16;         // 0..112
    const float* Wptr = W + (size_t)br * 256 + bn + bc;

    for (int k0 = 0; k0 < K; k0 += 32) {
        // load + tf32-convert A tile (128x32)
        #pragma unroll
        for (int j = 0; j < 4; j++) {
            float4 v = aok ? *(const float4*)(Aptr + k0 + j * 4)
                           : make_float4(0.f, 0.f, 0.f, 0.f);
            float4 t;
            t.x = __uint_as_float(f2tf32(v.x));
            t.y = __uint_as_float(f2tf32(v.y));
            t.z = __uint_as_float(f2tf32(v.z));
            t.w = __uint_as_float(f2tf32(v.w));
            *(float4*)&As[ar][ac + j * 4] = t;
        }
        // load + tf32-convert B tile (32x128)
        #pragma unroll
        for (int j = 0; j < 4; j++) {
            float4 v = *(const float4*)(Wptr + (size_t)k0 * 256 + j * 4);
            float4 t;
            t.x = __uint_as_float(f2tf32(v.x));
            t.y = __uint_as_float(f2tf32(v.y));
            t.z = __uint_as_float(f2tf32(v.z));
            t.w = __uint_as_float(f2tf32(v.w));
            *(float4*)&Bs[br][bc + j * 4] = t;
        }
        __syncthreads();

        #pragma unroll
        for (int ks = 0; ks < 4; ks++) {
            int kb = ks * 8;
            unsigned a[4][4], b[4][2];
            #pragma unroll
            for (int mt = 0; mt < 4; mt++) {
                int row = warp_m + mt * 16;
                a[mt][0] = __float_as_uint(As[row + gid][kb + tig]);
                a[mt][1] = __float_as_uint(As[row + gid + 8][kb + tig]);
                a[mt][2] = __float_as_uint(As[row + gid][kb + tig + 4]);
                a[mt][3] = __float_as_uint(As[row + gid + 8][kb + tig + 4]);
            }
            #pragma unroll
            for (int nt = 0; nt < 4; nt++) {
                int col = warp_n + nt * 8;
                b[nt][0] = __float_as_uint(Bs[kb + tig][col + gid]);
                b[nt][1] = __float_as_uint(Bs[kb + tig + 4][col + gid]);
            }
            #pragma unroll
            for (int mt = 0; mt < 4; mt++)
                #pragma unroll
                for (int nt = 0; nt < 4; nt++) {
                    asm volatile(
                        "mma.sync.aligned.m16n8k8.row.col.f32.tf32.tf32.f32 "
                        "{%0,%1,%2,%3}, {%4,%5,%6,%7}, {%8,%9}, {%0,%1,%2,%3};"
                        : "+f"(c[mt][nt][0]), "+f"(c[mt][nt][1]),
                          "+f"(c[mt][nt][2]), "+f"(c[mt][nt][3])
                        : "r"(a[mt][0]), "r"(a[mt][1]), "r"(a[mt][2]), "r"(a[mt][3]),
                          "r"(b[nt][0]), "r"(b[nt][1]));
                }
        }
        __syncthreads();
    }

    // epilogue
    #pragma unroll
    for (int mt = 0; mt < 4; mt++) {
        int r0 = bm + warp_m + mt * 16 + gid;
        #pragma unroll
        for (int nt = 0; nt < 4; nt++) {
            int col = bn + warp_n + nt * 8 + 2 * tig;
            float bx = 0.f, by = 0.f;
            if (bias) { bx = bias[col]; by = bias[col + 1]; }
            if (r0 < M) {
                float2 o0 = make_float2(c[mt][nt][0] + bx, c[mt][nt][1] + by);
                *(float2*)(C + (size_t)r0 * ldc + col) = o0;
            }
            if (r0 + 8 < M) {
                float2 o1 = make_float2(c[mt][nt][2] + bx, c[mt][nt][3] + by);
                *(float2*)(C + (size_t)(r0 + 8) * ldc + col) = o1;
            }
        }
    }
}

// ---------------- edge mean (CSR gather) + edge_proj ------------------------
__global__ void edgeproj_kernel(const float* __restrict__ eattr,
                                const float* __restrict__ Wep,
                                const float* __restrict__ bep) {
    __shared__ float sW[EDGE_DIM][256];
    __shared__ float snef[16][EDGE_DIM];
    int tid = threadIdx.x;
    for (int i = tid; i < EDGE_DIM * 256; i += 256)
        sW[i >> 8][i & 255] = Wep[i];

    int g = tid >> 4;       // node within block group (0..15)
    int j = tid & 15;       // edge-dim lane
    int n = blockIdx.x * 16 + g;

    float s = 0.f;
    int deg = 0;
    if (n < NN) {
        int off = g_off[n];
        deg = g_off[n + 1] - off;
        for (int e = 0; e < deg; e++) {
            int eid = g_eid[off + e];
            s += eattr[(size_t)eid * EDGE_DIM + j];
        }
    }
    snef[g][j] = s / fmaxf((float)deg, 1.0f);
    __syncthreads();

    if (n < NN) {
        int c0 = j * 16;
        float acc[16];
        #pragma unroll
        for (int c = 0; c < 16; c++) acc[c] = bep[c0 + c];
        #pragma unroll
        for (int k = 0; k < EDGE_DIM; k++) {
            float v = snef[g][k];
            #pragma unroll
            for (int c = 0; c < 16; c++) acc[c] += v * sW[k][c0 + c];
        }
        float* outp = g_xcat + (size_t)n * 512 + 256 + c0;
        #pragma unroll
        for (int c = 0; c < 16; c += 4)
            *(float4*)(outp + c) = make_float4(acc[c], acc[c + 1], acc[c + 2], acc[c + 3]);
    }
}

// ---------------- attention dot products ------------------------------------
__global__ void attn_dots(const float* __restrict__ as_p,
                          const float* __restrict__ ad_p) {
    int n = blockIdx.x;
    int h = threadIdx.x >> 5;
    int l = threadIdx.x & 31;
    const float* row = g_xh + (size_t)n * 256 + h * CH;
    float x0 = row[l], x1 = row[l + 32];
    float s = x0 * as_p[h * CH + l] + x1 * as_p[h * CH + l + 32];
    float d = x0 * ad_p[h * CH + l] + x1 * ad_p[h * CH + l + 32];
    s = wredsum(s);
    d = wredsum(d);
    if (l == 0) {
        g_asrc[n * HEADS + h] = s;
        g_adst[n * HEADS + h] = d;
    }
}

// ---------------- GAT aggregation (R2 version: known-good perf) --------------
__global__ void gat_aggregate(const float* __restrict__ bias,
                              float* __restrict__ out) {
    int n = blockIdx.x;
    int h = threadIdx.x >> 5;
    int l = threadIdx.x & 31;
    int off = g_off[n];
    int deg = g_off[n + 1] - off;
    float adst = g_adst[n * HEADS + h];
    float slf = lrelu(g_asrc[n * HEADS + h] + adst);

    // pass 1: max
    float m = slf;
    for (int e = l; e < deg; e += 32) {
        int s = g_csr[off + e];
        m = fmaxf(m, lrelu(g_asrc[s * HEADS + h] + adst));
    }
    m = wredmax(m);

    // pass 2: denom
    float ds = 0.f;
    for (int e = l; e < deg; e += 32) {
        int s = g_csr[off + e];
        ds += expf(lrelu(g_asrc[s * HEADS + h] + adst) - m);
    }
    ds = wredsum(ds) + expf(slf - m);
    float inv = 1.0f / ds;

    // pass 3: weighted gather
    const float* xr = g_xh + (size_t)n * 256 + h * CH;
    float wslf = expf(slf - m) * inv;
    float a0 = wslf * xr[l];
    float a1 = wslf * xr[l + 32];
    int e = 0;
    for (; e + 1 < deg; e += 2) {
        int s0 = g_csr[off + e];
        int s1 = g_csr[off + e + 1];
        float w0 = expf(lrelu(g_asrc[s0 * HEADS + h] + adst) - m) * inv;
        float w1 = expf(lrelu(g_asrc[s1 * HEADS + h] + adst) - m) * inv;
        const float* r0 = g_xh + (size_t)s0 * 256 + h * CH;
        const float* r1 = g_xh + (size_t)s1 * 256 + h * CH;
        a0 += w0 * r0[l] + w1 * r1[l];
        a1 += w0 * r0[l + 32] + w1 * r1[l + 32];
    }
    if (e < deg) {
        int s0 = g_csr[off + e];
        float w0 = expf(lrelu(g_asrc[s0 * HEADS + h] + adst) - m) * inv;
        const float* r0 = g_xh + (size_t)s0 * 256 + h * CH;
        a0 += w0 * r0[l];
        a1 += w0 * r0[l + 32];
    }
    float b0 = bias[h * CH + l];
    float b1 = bias[h * CH + l + 32];
    out[(size_t)n * 256 + h * CH + l]      = elu(a0 + b0);
    out[(size_t)n * 256 + h * CH + l + 32] = elu(a1 + b1);
}

// ---------------- launch ----------------------------------------------------
extern "C" void kernel_launch(void* const* d_in, const int* in_sizes, int n_in,
                              void* d_out, int out_size) {
    const float* node_feats = (const float*)d_in[0];
    const float* edge_attr  = (const float*)d_in[1];
    const float* Wnp = (const float*)d_in[2];
    const float* bnp = (const float*)d_in[3];
    const float* Wep = (const float*)d_in[4];
    const float* bep = (const float*)d_in[5];
    const float* Wg1 = (const float*)d_in[6];
    const float* as1 = (const float*)d_in[7];
    const float* ad1 = (const float*)d_in[8];
    const float* bg1 = (const float*)d_in[9];
    const float* Wg2 = (const float*)d_in[10];
    const float* as2 = (const float*)d_in[11];
    const float* ad2 = (const float*)d_in[12];
    const float* bg2 = (const float*)d_in[13];
    const float* Wo  = (const float*)d_in[14];
    const float* bo  = (const float*)d_in[15];
    const int* ei_raw = (const int*)d_in[16];
    float* out = (float*)d_out;

    float* xcat; cudaGetSymbolAddress((void**)&xcat, g_xcat);
    float* xh;   cudaGetSymbolAddress((void**)&xh,   g_xh);
    float* hbuf; cudaGetSymbolAddress((void**)&hbuf, g_h);

    const int EB = (EE + 255) / 256;

    detect_kernel<<<1, 32>>>(ei_raw);
    convert_edges<<<EB, 256>>>(ei_raw);

    zero_cnt<<<(NN + 255) / 256, 256>>>();
    edge_count<<<EB, 256>>>();
    prefix_kernel<<<1, 1024>>>();
    edge_fill_csr<<<EB, 256>>>();

    dim3 ggrid(2, (NN + 127) / 128);

    // node_proj -> xcat[:, :256]
    gemm_tf32<<<ggrid, 256>>>(node_feats, NODE_IN, Wnp, bnp, xcat, 512, NN, NODE_IN);
    // edge mean + edge_proj -> xcat[:, 256:512]
    edgeproj_kernel<<<(NN + 15) / 16, 256>>>(edge_attr, Wep, bep);

    // ---- GAT layer 1 ----
    gemm_tf32<<<ggrid, 256>>>(xcat, 512, Wg1, nullptr, xh, 256, NN, 512);
    attn_dots<<<NN, 128>>>(as1, ad1);
    gat_aggregate<<<NN, 128>>>(bg1, hbuf);

    // ---- GAT layer 2 ----
    gemm_tf32<<<ggrid, 256>>>(hbuf, 256, Wg2, nullptr, xh, 256, NN, 256);
    attn_dots<<<NN, 128>>>(as2, ad2);
    gat_aggregate<<<NN, 128>>>(bg2, hbuf);

    // ---- out_proj -> d_out ----
    gemm_tf32<<<ggrid, 256>>>(hbuf, 256, Wo, bo, out, 256, NN, 256);
}

// round 7
// speedup vs baseline: 2.0578x; 1.0634x over previous
#include <cuda_runtime.h>
#include <cuda_bf16.h>
#include <math.h>

#define NN 50000
#define EE 800000
#define NODE_IN 128
#define HID 256
#define OUT_D 256
#define EDGE_DIM 16
#define HEADS 4
#define CH 64

// ---------------- scratch (static device globals) ---------------------------
__device__ float g_xcat[(size_t)NN * 512];
__device__ float g_xh[(size_t)NN * 256];
__device__ float g_h[(size_t)NN * 256];
__device__ int   g_cnt[NN];
__device__ int   g_off[NN + 1];
__device__ int   g_cur[NN];
__device__ int   g_csr[EE];     // src node per CSR slot
__device__ int   g_eid[EE];     // edge id per CSR slot
__device__ float g_asrc[NN * HEADS];
__device__ float g_adst[NN * HEADS];
__device__ int   g_src[EE];
__device__ int   g_dst[EE];
__device__ int   g_is64;

// ---------------- helpers ---------------------------------------------------
__device__ __forceinline__ float lrelu(float x) { return x > 0.f ? x : 0.2f * x; }
__device__ __forceinline__ float elu(float x)   { return x > 0.f ? x : expf(x) - 1.f; }
__device__ __forceinline__ float wredsum(float v) {
    #pragma unroll
    for (int o = 16; o; o >>= 1) v += __shfl_xor_sync(0xffffffffu, v, o);
    return v;
}
__device__ __forceinline__ unsigned f2tf32(float x) {
    unsigned u;
    asm("cvt.rna.tf32.f32 %0, %1;" : "=r"(u) : "f"(x));
    return u;
}

// ---------------- edge index normalization ---------------------------------
__global__ void detect_kernel(const int* __restrict__ ei_raw) {
    if (threadIdx.x == 0) {
        int any = 0;
        #pragma unroll 1
        for (int i = 1; i < 256; i += 2) any |= ei_raw[i];
        g_is64 = (any == 0) ? 1 : 0;
    }
}

__global__ void zero_cnt() {
    int i = blockIdx.x * blockDim.x + threadIdx.x;
    if (i < NN) g_cnt[i] = 0;
}

// convert + degree count fused
__global__ void convert_edges(const int* __restrict__ ei_raw) {
    int e = blockIdx.x * blockDim.x + threadIdx.x;
    if (e >= EE) return;
    int s, d;
    if (g_is64) {
        s = ei_raw[2 * (size_t)e];
        d = ei_raw[2 * ((size_t)EE + e)];
    } else {
        s = ei_raw[e];
        d = ei_raw[EE + e];
    }
    s = min(max(s, 0), NN - 1);
    d = min(max(d, 0), NN - 1);
    g_src[e] = s;
    g_dst[e] = d;
    atomicAdd(&g_cnt[d], 1);
}

__global__ void prefix_kernel() {
    __shared__ int sh[1024];
    const int CHK = (NN + 1023) / 1024;  // 49
    int t = threadIdx.x;
    int start = t * CHK;
    int stop = min(start + CHK, NN);
    int s = 0;
    for (int i = start; i < stop; i++) s += g_cnt[i];
    sh[t] = s;
    __syncthreads();
    #pragma unroll
    for (int off = 1; off < 1024; off <<= 1) {
        int v = (t >= off) ? sh[t - off] : 0;
        __syncthreads();
        sh[t] += v;
        __syncthreads();
    }
    int run = sh[t] - s;
    for (int i = start; i < stop; i++) {
        g_off[i] = run;
        g_cur[i] = run;
        run += g_cnt[i];
    }
    if (t == 1023) g_off[NN] = sh[1023];
}

__global__ void edge_fill_csr() {
    int e = blockIdx.x * blockDim.x + threadIdx.x;
    if (e >= EE) return;
    int pos = atomicAdd(&g_cur[g_dst[e]], 1);
    g_csr[pos] = g_src[e];
    g_eid[pos] = e;
}

// ---------------- tf32 tensor-core GEMM (unchanged from R5) -----------------
__global__ void __launch_bounds__(256, 2)
gemm_tf32(const float* __restrict__ A, int lda,
          const float* __restrict__ W,
          const float* __restrict__ bias,
          float* __restrict__ C, int ldc,
          int M, int K) {
    __shared__ float As[128][36];
    __shared__ float Bs[32][136];

    int bm = blockIdx.y * 128;
    int bn = blockIdx.x * 128;
    int tid = threadIdx.x;
    int wid = tid >> 5;
    int lane = tid & 31;
    int gid = lane >> 2;
    int tig = lane & 3;
    int warp_m = (wid & 1) * 64;
    int warp_n = (wid >> 1) * 32;

    float c[4][4][4];
    #pragma unroll
    for (int i = 0; i < 4; i++)
        #pragma unroll
        for (int j = 0; j < 4; j++)
            #pragma unroll
            for (int r = 0; r < 4; r++) c[i][j][r] = 0.f;

    int ar = tid >> 1;
    int ac = (tid & 1) * 16;
    bool aok = (bm + ar) < M;
    const float* Aptr = A + (size_t)(bm + ar) * lda + ac;
    int br = tid >> 3;
    int bc = (tid & 7) * 16;
    const float* Wptr = W + (size_t)br * 256 + bn + bc;

    for (int k0 = 0; k0 < K; k0 += 32) {
        #pragma unroll
        for (int j = 0; j < 4; j++) {
            float4 v = aok ? *(const float4*)(Aptr + k0 + j * 4)
                           : make_float4(0.f, 0.f, 0.f, 0.f);
            float4 t;
            t.x = __uint_as_float(f2tf32(v.x));
            t.y = __uint_as_float(f2tf32(v.y));
            t.z = __uint_as_float(f2tf32(v.z));
            t.w = __uint_as_float(f2tf32(v.w));
            *(float4*)&As[ar][ac + j * 4] = t;
        }
        #pragma unroll
        for (int j = 0; j < 4; j++) {
            float4 v = *(const float4*)(Wptr + (size_t)k0 * 256 + j * 4);
            float4 t;
            t.x = __uint_as_float(f2tf32(v.x));
            t.y = __uint_as_float(f2tf32(v.y));
            t.z = __uint_as_float(f2tf32(v.z));
            t.w = __uint_as_float(f2tf32(v.w));
            *(float4*)&Bs[br][bc + j * 4] = t;
        }
        __syncthreads();

        #pragma unroll
        for (int ks = 0; ks < 4; ks++) {
            int kb = ks * 8;
            unsigned a[4][4], b[4][2];
            #pragma unroll
            for (int mt = 0; mt < 4; mt++) {
                int row = warp_m + mt * 16;
                a[mt][0] = __float_as_uint(As[row + gid][kb + tig]);
                a[mt][1] = __float_as_uint(As[row + gid + 8][kb + tig]);
                a[mt][2] = __float_as_uint(As[row + gid][kb + tig + 4]);
                a[mt][3] = __float_as_uint(As[row + gid + 8][kb + tig + 4]);
            }
            #pragma unroll
            for (int nt = 0; nt < 4; nt++) {
                int col = warp_n + nt * 8;
                b[nt][0] = __float_as_uint(Bs[kb + tig][col + gid]);
                b[nt][1] = __float_as_uint(Bs[kb + tig + 4][col + gid]);
            }
            #pragma unroll
            for (int mt = 0; mt < 4; mt++)
                #pragma unroll
                for (int nt = 0; nt < 4; nt++) {
                    asm volatile(
                        "mma.sync.aligned.m16n8k8.row.col.f32.tf32.tf32.f32 "
                        "{%0,%1,%2,%3}, {%4,%5,%6,%7}, {%8,%9}, {%0,%1,%2,%3};"
                        : "+f"(c[mt][nt][0]), "+f"(c[mt][nt][1]),
                          "+f"(c[mt][nt][2]), "+f"(c[mt][nt][3])
                        : "r"(a[mt][0]), "r"(a[mt][1]), "r"(a[mt][2]), "r"(a[mt][3]),
                          "r"(b[nt][0]), "r"(b[nt][1]));
                }
        }
        __syncthreads();
    }

    #pragma unroll
    for (int mt = 0; mt < 4; mt++) {
        int r0 = bm + warp_m + mt * 16 + gid;
        #pragma unroll
        for (int nt = 0; nt < 4; nt++) {
            int col = bn + warp_n + nt * 8 + 2 * tig;
            float bx = 0.f, by = 0.f;
            if (bias) { bx = bias[col]; by = bias[col + 1]; }
            if (r0 < M) {
                float2 o0 = make_float2(c[mt][nt][0] + bx, c[mt][nt][1] + by);
                *(float2*)(C + (size_t)r0 * ldc + col) = o0;
            }
            if (r0 + 8 < M) {
                float2 o1 = make_float2(c[mt][nt][2] + bx, c[mt][nt][3] + by);
                *(float2*)(C + (size_t)(r0 + 8) * ldc + col) = o1;
            }
        }
    }
}

// ---------------- edge mean (CSR gather) + edge_proj ------------------------
__global__ void edgeproj_kernel(const float* __restrict__ eattr,
                                const float* __restrict__ Wep,
                                const float* __restrict__ bep) {
    __shared__ float sW[EDGE_DIM][256];
    __shared__ float snef[16][EDGE_DIM];
    int tid = threadIdx.x;
    for (int i = tid; i < EDGE_DIM * 256; i += 256)
        sW[i >> 8][i & 255] = Wep[i];

    int g = tid >> 4;
    int j = tid & 15;
    int n = blockIdx.x * 16 + g;

    float s = 0.f;
    int deg = 0;
    if (n < NN) {
        int off = g_off[n];
        deg = g_off[n + 1] - off;
        for (int e = 0; e < deg; e++) {
            int eid = g_eid[off + e];
            s += eattr[(size_t)eid * EDGE_DIM + j];
        }
    }
    snef[g][j] = s / fmaxf((float)deg, 1.0f);
    __syncthreads();

    if (n < NN) {
        int c0 = j * 16;
        float acc[16];
        #pragma unroll
        for (int c = 0; c < 16; c++) acc[c] = bep[c0 + c];
        #pragma unroll
        for (int k = 0; k < EDGE_DIM; k++) {
            float v = snef[g][k];
            #pragma unroll
            for (int c = 0; c < 16; c++) acc[c] += v * sW[k][c0 + c];
        }
        float* outp = g_xcat + (size_t)n * 512 + 256 + c0;
        #pragma unroll
        for (int c = 0; c < 16; c += 4)
            *(float4*)(outp + c) = make_float4(acc[c], acc[c + 1], acc[c + 2], acc[c + 3]);
    }
}

// ---------------- attention dot products ------------------------------------
__global__ void attn_dots(const float* __restrict__ as_p,
                          const float* __restrict__ ad_p) {
    int n = blockIdx.x;
    int h = threadIdx.x >> 5;
    int l = threadIdx.x & 31;
    const float* row = g_xh + (size_t)n * 256 + h * CH;
    float x0 = row[l], x1 = row[l + 32];
    float s = x0 * as_p[h * CH + l] + x1 * as_p[h * CH + l + 32];
    float d = x0 * ad_p[h * CH + l] + x1 * ad_p[h * CH + l + 32];
    s = wredsum(s);
    d = wredsum(d);
    if (l == 0) {
        g_asrc[n * HEADS + h] = s;
        g_adst[n * HEADS + h] = d;
    }
}

// ---------------- GAT aggregation: SINGLE pass, shift-free softmax ----------
// softmax is shift-invariant; logits here are small (|.| << 60), so we use
// unshifted exp (clamped at 60 for safety). Denominator is accumulated
// redundantly+identically on all lanes -> no reductions at all.
__global__ void gat_aggregate(const float* __restrict__ bias,
                              float* __restrict__ out) {
    int n = blockIdx.x;
    int h = threadIdx.x >> 5;
    int l = threadIdx.x & 31;
    int off = g_off[n];
    int deg = g_off[n + 1] - off;
    float adst = g_adst[n * HEADS + h];

    // self-loop term
    const float* xr = g_xh + (size_t)n * 256 + h * CH;
    float wslf = expf(fminf(lrelu(g_asrc[n * HEADS + h] + adst), 60.f));
    float ds = wslf;
    float a0 = wslf * xr[l];
    float a1 = wslf * xr[l + 32];

    int e = 0;
    for (; e + 1 < deg; e += 2) {
        int s0 = g_csr[off + e];
        int s1 = g_csr[off + e + 1];
        float w0 = expf(fminf(lrelu(g_asrc[s0 * HEADS + h] + adst), 60.f));
        float w1 = expf(fminf(lrelu(g_asrc[s1 * HEADS + h] + adst), 60.f));
        const float* r0 = g_xh + (size_t)s0 * 256 + h * CH;
        const float* r1 = g_xh + (size_t)s1 * 256 + h * CH;
        float v00 = r0[l], v01 = r0[l + 32];
        float v10 = r1[l], v11 = r1[l + 32];
        ds += w0 + w1;
        a0 += w0 * v00 + w1 * v10;
        a1 += w0 * v01 + w1 * v11;
    }
    if (e < deg) {
        int s0 = g_csr[off + e];
        float w0 = expf(fminf(lrelu(g_asrc[s0 * HEADS + h] + adst), 60.f));
        const float* r0 = g_xh + (size_t)s0 * 256 + h * CH;
        ds += w0;
        a0 += w0 * r0[l];
        a1 += w0 * r0[l + 32];
    }

    float inv = 1.0f / ds;
    float b0 = bias[h * CH + l];
    float b1 = bias[h * CH + l + 32];
    out[(size_t)n * 256 + h * CH + l]      = elu(a0 * inv + b0);
    out[(size_t)n * 256 + h * CH + l + 32] = elu(a1 * inv + b1);
}

// ---------------- launch ----------------------------------------------------
extern "C" void kernel_launch(void* const* d_in, const int* in_sizes, int n_in,
                              void* d_out, int out_size) {
    const float* node_feats = (const float*)d_in[0];
    const float* edge_attr  = (const float*)d_in[1];
    const float* Wnp = (const float*)d_in[2];
    const float* bnp = (const float*)d_in[3];
    const float* Wep = (const float*)d_in[4];
    const float* bep = (const float*)d_in[5];
    const float* Wg1 = (const float*)d_in[6];
    const float* as1 = (const float*)d_in[7];
    const float* ad1 = (const float*)d_in[8];
    const float* bg1 = (const float*)d_in[9];
    const float* Wg2 = (const float*)d_in[10];
    const float* as2 = (const float*)d_in[11];
    const float* ad2 = (const float*)d_in[12];
    const float* bg2 = (const float*)d_in[13];
    const float* Wo  = (const float*)d_in[14];
    const float* bo  = (const float*)d_in[15];
    const int* ei_raw = (const int*)d_in[16];
    float* out = (float*)d_out;

    float* xcat; cudaGetSymbolAddress((void**)&xcat, g_xcat);
    float* xh;   cudaGetSymbolAddress((void**)&xh,   g_xh);
    float* hbuf; cudaGetSymbolAddress((void**)&hbuf, g_h);

    const int EB = (EE + 255) / 256;

    detect_kernel<<<1, 32>>>(ei_raw);
    zero_cnt<<<(NN + 255) / 256, 256>>>();
    convert_edges<<<EB, 256>>>(ei_raw);   // also counts degrees
    prefix_kernel<<<1, 1024>>>();
    edge_fill_csr<<<EB, 256>>>();

    dim3 ggrid(2, (NN + 127) / 128);

    // node_proj -> xcat[:, :256]
    gemm_tf32<<<ggrid, 256>>>(node_feats, NODE_IN, Wnp, bnp, xcat, 512, NN, NODE_IN);
    // edge mean + edge_proj -> xcat[:, 256:512]
    edgeproj_kernel<<<(NN + 15) / 16, 256>>>(edge_attr, Wep, bep);

    // ---- GAT layer 1 ----
    gemm_tf32<<<ggrid, 256>>>(xcat, 512, Wg1, nullptr, xh, 256, NN, 512);
    attn_dots<<<NN, 128>>>(as1, ad1);
    gat_aggregate<<<NN, 128>>>(bg1, hbuf);

    // ---- GAT layer 2 ----
    gemm_tf32<<<ggrid, 256>>>(hbuf, 256, Wg2, nullptr, xh, 256, NN, 256);
    attn_dots<<<NN, 128>>>(as2, ad2);
    gat_aggregate<<<NN, 128>>>(bg2, hbuf);

    // ---- out_proj -> d_out ----
    gemm_tf32<<<ggrid, 256>>>(hbuf, 256, Wo, bo, out, 256, NN, 256);
}

// round 8
// speedup vs baseline: 2.2260x; 1.0818x over previous
#include <cuda_runtime.h>
#include <cuda_bf16.h>
#include <math.h>

#define NN 50000
#define EE 800000
#define NODE_IN 128
#define HID 256
#define OUT_D 256
#define EDGE_DIM 16
#define HEADS 4
#define CH 64

#define SCAN_B 256
#define NBLK ((NN + SCAN_B - 1) / SCAN_B)   // 196

// ---------------- scratch (static device globals) ---------------------------
__device__ float g_xcat[(size_t)NN * 512];
__device__ float g_xh[(size_t)NN * 256];
__device__ float g_h[(size_t)NN * 256];
__device__ int   g_cnt[NN];
__device__ int   g_off[NN + 1];
__device__ int   g_cur[NN];
__device__ int   g_csr[EE];     // src node per CSR slot
__device__ int   g_eid[EE];     // edge id per CSR slot
__device__ float g_asrc[NN * HEADS];
__device__ float g_adst[NN * HEADS];
__device__ int   g_src[EE];
__device__ int   g_dst[EE];
__device__ int   g_is64;
__device__ int   g_blk[NBLK];
__device__ int   g_blkoff[NBLK];

// ---------------- helpers ---------------------------------------------------
__device__ __forceinline__ float lrelu(float x) { return x > 0.f ? x : 0.2f * x; }
__device__ __forceinline__ float elu(float x)   { return x > 0.f ? x : expf(x) - 1.f; }
__device__ __forceinline__ float wredsum(float v) {
    #pragma unroll
    for (int o = 16; o; o >>= 1) v += __shfl_xor_sync(0xffffffffu, v, o);
    return v;
}
__device__ __forceinline__ unsigned f2tf32(float x) {
    unsigned u;
    asm("cvt.rna.tf32.f32 %0, %1;" : "=r"(u) : "f"(x));
    return u;
}

// ---------------- edge index normalization ---------------------------------
__global__ void detect_kernel(const int* __restrict__ ei_raw) {
    if (threadIdx.x == 0) {
        int any = 0;
        #pragma unroll 1
        for (int i = 1; i < 256; i += 2) any |= ei_raw[i];
        g_is64 = (any == 0) ? 1 : 0;
    }
}

__global__ void zero_cnt() {
    int i = blockIdx.x * blockDim.x + threadIdx.x;
    if (i < NN) g_cnt[i] = 0;
}

// convert + degree count fused
__global__ void convert_edges(const int* __restrict__ ei_raw) {
    int e = blockIdx.x * blockDim.x + threadIdx.x;
    if (e >= EE) return;
    int s, d;
    if (g_is64) {
        s = ei_raw[2 * (size_t)e];
        d = ei_raw[2 * ((size_t)EE + e)];
    } else {
        s = ei_raw[e];
        d = ei_raw[EE + e];
    }
    s = min(max(s, 0), NN - 1);
    d = min(max(d, 0), NN - 1);
    g_src[e] = s;
    g_dst[e] = d;
    atomicAdd(&g_cnt[d], 1);
}

// ---------------- hierarchical scan (3 tiny parallel kernels) ---------------
// phase 1: per-block exclusive scan of g_cnt, write local prefix + block total
__global__ void scan1() {
    __shared__ int sh[SCAN_B];
    int t = threadIdx.x;
    int n = blockIdx.x * SCAN_B + t;
    int v = (n < NN) ? g_cnt[n] : 0;
    sh[t] = v;
    __syncthreads();
    #pragma unroll
    for (int off = 1; off < SCAN_B; off <<= 1) {
        int u = (t >= off) ? sh[t - off] : 0;
        __syncthreads();
        sh[t] += u;
        __syncthreads();
    }
    if (n < NN) g_off[n] = sh[t] - v;   // local exclusive prefix
    if (t == SCAN_B - 1) g_blk[blockIdx.x] = sh[t];
}

// phase 2: single-block scan of the NBLK block totals
__global__ void scan2() {
    __shared__ int sh[SCAN_B];
    int t = threadIdx.x;
    int v = (t < NBLK) ? g_blk[t] : 0;
    sh[t] = v;
    __syncthreads();
    #pragma unroll
    for (int off = 1; off < SCAN_B; off <<= 1) {
        int u = (t >= off) ? sh[t - off] : 0;
        __syncthreads();
        sh[t] += u;
        __syncthreads();
    }
    if (t < NBLK) g_blkoff[t] = sh[t] - v;  // exclusive
    if (t == SCAN_B - 1) g_off[NN] = sh[t]; // total (== EE)
}

// phase 3: add block offsets, init g_cur
__global__ void scan3() {
    int n = blockIdx.x * SCAN_B + threadIdx.x;
    if (n >= NN) return;
    int o = g_off[n] + g_blkoff[blockIdx.x];
    g_off[n] = o;
    g_cur[n] = o;
}

__global__ void edge_fill_csr() {
    int e = blockIdx.x * blockDim.x + threadIdx.x;
    if (e >= EE) return;
    int pos = atomicAdd(&g_cur[g_dst[e]], 1);
    g_csr[pos] = g_src[e];
    g_eid[pos] = e;
}

// ---------------- tf32 tensor-core GEMM (unchanged) -------------------------
__global__ void __launch_bounds__(256, 2)
gemm_tf32(const float* __restrict__ A, int lda,
          const float* __restrict__ W,
          const float* __restrict__ bias,
          float* __restrict__ C, int ldc,
          int M, int K) {
    __shared__ float As[128][36];
    __shared__ float Bs[32][136];

    int bm = blockIdx.y * 128;
    int bn = blockIdx.x * 128;
    int tid = threadIdx.x;
    int wid = tid >> 5;
    int lane = tid & 31;
    int gid = lane >> 2;
    int tig = lane & 3;
    int warp_m = (wid & 1) * 64;
    int warp_n = (wid >> 1) * 32;

    float c[4][4][4];
    #pragma unroll
    for (int i = 0; i < 4; i++)
        #pragma unroll
        for (int j = 0; j < 4; j++)
            #pragma unroll
            for (int r = 0; r < 4; r++) c[i][j][r] = 0.f;

    int ar = tid >> 1;
    int ac = (tid & 1) * 16;
    bool aok = (bm + ar) < M;
    const float* Aptr = A + (size_t)(bm + ar) * lda + ac;
    int br = tid >> 3;
    int bc = (tid & 7) * 16;
    const float* Wptr = W + (size_t)br * 256 + bn + bc;

    for (int k0 = 0; k0 < K; k0 += 32) {
        #pragma unroll
        for (int j = 0; j < 4; j++) {
            float4 v = aok ? *(const float4*)(Aptr + k0 + j * 4)
                           : make_float4(0.f, 0.f, 0.f, 0.f);
            float4 t;
            t.x = __uint_as_float(f2tf32(v.x));
            t.y = __uint_as_float(f2tf32(v.y));
            t.z = __uint_as_float(f2tf32(v.z));
            t.w = __uint_as_float(f2tf32(v.w));
            *(float4*)&As[ar][ac + j * 4] = t;
        }
        #pragma unroll
        for (int j = 0; j < 4; j++) {
            float4 v = *(const float4*)(Wptr + (size_t)k0 * 256 + j * 4);
            float4 t;
            t.x = __uint_as_float(f2tf32(v.x));
            t.y = __uint_as_float(f2tf32(v.y));
            t.z = __uint_as_float(f2tf32(v.z));
            t.w = __uint_as_float(f2tf32(v.w));
            *(float4*)&Bs[br][bc + j * 4] = t;
        }
        __syncthreads();

        #pragma unroll
        for (int ks = 0; ks < 4; ks++) {
            int kb = ks * 8;
            unsigned a[4][4], b[4][2];
            #pragma unroll
            for (int mt = 0; mt < 4; mt++) {
                int row = warp_m + mt * 16;
                a[mt][0] = __float_as_uint(As[row + gid][kb + tig]);
                a[mt][1] = __float_as_uint(As[row + gid + 8][kb + tig]);
                a[mt][2] = __float_as_uint(As[row + gid][kb + tig + 4]);
                a[mt][3] = __float_as_uint(As[row + gid + 8][kb + tig + 4]);
            }
            #pragma unroll
            for (int nt = 0; nt < 4; nt++) {
                int col = warp_n + nt * 8;
                b[nt][0] = __float_as_uint(Bs[kb + tig][col + gid]);
                b[nt][1] = __float_as_uint(Bs[kb + tig + 4][col + gid]);
            }
            #pragma unroll
            for (int mt = 0; mt < 4; mt++)
                #pragma unroll
                for (int nt = 0; nt < 4; nt++) {
                    asm volatile(
                        "mma.sync.aligned.m16n8k8.row.col.f32.tf32.tf32.f32 "
                        "{%0,%1,%2,%3}, {%4,%5,%6,%7}, {%8,%9}, {%0,%1,%2,%3};"
                        : "+f"(c[mt][nt][0]), "+f"(c[mt][nt][1]),
                          "+f"(c[mt][nt][2]), "+f"(c[mt][nt][3])
                        : "r"(a[mt][0]), "r"(a[mt][1]), "r"(a[mt][2]), "r"(a[mt][3]),
                          "r"(b[nt][0]), "r"(b[nt][1]));
                }
        }
        __syncthreads();
    }

    #pragma unroll
    for (int mt = 0; mt < 4; mt++) {
        int r0 = bm + warp_m + mt * 16 + gid;
        #pragma unroll
        for (int nt = 0; nt < 4; nt++) {
            int col = bn + warp_n + nt * 8 + 2 * tig;
            float bx = 0.f, by = 0.f;
            if (bias) { bx = bias[col]; by = bias[col + 1]; }
            if (r0 < M) {
                float2 o0 = make_float2(c[mt][nt][0] + bx, c[mt][nt][1] + by);
                *(float2*)(C + (size_t)r0 * ldc + col) = o0;
            }
            if (r0 + 8 < M) {
                float2 o1 = make_float2(c[mt][nt][2] + bx, c[mt][nt][3] + by);
                *(float2*)(C + (size_t)(r0 + 8) * ldc + col) = o1;
            }
        }
    }
}

// ---------------- edge mean (CSR gather) + edge_proj ------------------------
__global__ void edgeproj_kernel(const float* __restrict__ eattr,
                                const float* __restrict__ Wep,
                                const float* __restrict__ bep) {
    __shared__ float sW[EDGE_DIM][256];
    __shared__ float snef[16][EDGE_DIM];
    int tid = threadIdx.x;
    for (int i = tid; i < EDGE_DIM * 256; i += 256)
        sW[i >> 8][i & 255] = Wep[i];

    int g = tid >> 4;
    int j = tid & 15;
    int n = blockIdx.x * 16 + g;

    float s = 0.f;
    int deg = 0;
    if (n < NN) {
        int off = g_off[n];
        deg = g_off[n + 1] - off;
        for (int e = 0; e < deg; e++) {
            int eid = g_eid[off + e];
            s += eattr[(size_t)eid * EDGE_DIM + j];
        }
    }
    snef[g][j] = s / fmaxf((float)deg, 1.0f);
    __syncthreads();

    if (n < NN) {
        int c0 = j * 16;
        float acc[16];
        #pragma unroll
        for (int c = 0; c < 16; c++) acc[c] = bep[c0 + c];
        #pragma unroll
        for (int k = 0; k < EDGE_DIM; k++) {
            float v = snef[g][k];
            #pragma unroll
            for (int c = 0; c < 16; c++) acc[c] += v * sW[k][c0 + c];
        }
        float* outp = g_xcat + (size_t)n * 512 + 256 + c0;
        #pragma unroll
        for (int c = 0; c < 16; c += 4)
            *(float4*)(outp + c) = make_float4(acc[c], acc[c + 1], acc[c + 2], acc[c + 3]);
    }
}

// ---------------- attention dot products ------------------------------------
__global__ void attn_dots(const float* __restrict__ as_p,
                          const float* __restrict__ ad_p) {
    int n = blockIdx.x;
    int h = threadIdx.x >> 5;
    int l = threadIdx.x & 31;
    const float* row = g_xh + (size_t)n * 256 + h * CH;
    float x0 = row[l], x1 = row[l + 32];
    float s = x0 * as_p[h * CH + l] + x1 * as_p[h * CH + l + 32];
    float d = x0 * ad_p[h * CH + l] + x1 * ad_p[h * CH + l + 32];
    s = wredsum(s);
    d = wredsum(d);
    if (l == 0) {
        g_asrc[n * HEADS + h] = s;
        g_adst[n * HEADS + h] = d;
    }
}

// ---------------- GAT aggregation: single pass, shift-free softmax ----------
__global__ void gat_aggregate(const float* __restrict__ bias,
                              float* __restrict__ out) {
    int n = blockIdx.x;
    int h = threadIdx.x >> 5;
    int l = threadIdx.x & 31;
    int off = g_off[n];
    int deg = g_off[n + 1] - off;
    float adst = g_adst[n * HEADS + h];

    const float* xr = g_xh + (size_t)n * 256 + h * CH;
    float wslf = expf(fminf(lrelu(g_asrc[n * HEADS + h] + adst), 60.f));
    float ds = wslf;
    float a0 = wslf * xr[l];
    float a1 = wslf * xr[l + 32];

    int e = 0;
    for (; e + 1 < deg; e += 2) {
        int s0 = g_csr[off + e];
        int s1 = g_csr[off + e + 1];
        float w0 = expf(fminf(lrelu(g_asrc[s0 * HEADS + h] + adst), 60.f));
        float w1 = expf(fminf(lrelu(g_asrc[s1 * HEADS + h] + adst), 60.f));
        const float* r0 = g_xh + (size_t)s0 * 256 + h * CH;
        const float* r1 = g_xh + (size_t)s1 * 256 + h * CH;
        float v00 = r0[l], v01 = r0[l + 32];
        float v10 = r1[l], v11 = r1[l + 32];
        ds += w0 + w1;
        a0 += w0 * v00 + w1 * v10;
        a1 += w0 * v01 + w1 * v11;
    }
    if (e < deg) {
        int s0 = g_csr[off + e];
        float w0 = expf(fminf(lrelu(g_asrc[s0 * HEADS + h] + adst), 60.f));
        const float* r0 = g_xh + (size_t)s0 * 256 + h * CH;
        ds += w0;
        a0 += w0 * r0[l];
        a1 += w0 * r0[l + 32];
    }

    float inv = 1.0f / ds;
    float b0 = bias[h * CH + l];
    float b1 = bias[h * CH + l + 32];
    out[(size_t)n * 256 + h * CH + l]      = elu(a0 * inv + b0);
    out[(size_t)n * 256 + h * CH + l + 32] = elu(a1 * inv + b1);
}

// ---------------- launch ----------------------------------------------------
extern "C" void kernel_launch(void* const* d_in, const int* in_sizes, int n_in,
                              void* d_out, int out_size) {
    const float* node_feats = (const float*)d_in[0];
    const float* edge_attr  = (const float*)d_in[1];
    const float* Wnp = (const float*)d_in[2];
    const float* bnp = (const float*)d_in[3];
    const float* Wep = (const float*)d_in[4];
    const float* bep = (const float*)d_in[5];
    const float* Wg1 = (const float*)d_in[6];
    const float* as1 = (const float*)d_in[7];
    const float* ad1 = (const float*)d_in[8];
    const float* bg1 = (const float*)d_in[9];
    const float* Wg2 = (const float*)d_in[10];
    const float* as2 = (const float*)d_in[11];
    const float* ad2 = (const float*)d_in[12];
    const float* bg2 = (const float*)d_in[13];
    const float* Wo  = (const float*)d_in[14];
    const float* bo  = (const float*)d_in[15];
    const int* ei_raw = (const int*)d_in[16];
    float* out = (float*)d_out;

    float* xcat; cudaGetSymbolAddress((void**)&xcat, g_xcat);
    float* xh;   cudaGetSymbolAddress((void**)&xh,   g_xh);
    float* hbuf; cudaGetSymbolAddress((void**)&hbuf, g_h);

    const int EB = (EE + 255) / 256;

    detect_kernel<<<1, 32>>>(ei_raw);
    zero_cnt<<<NBLK, SCAN_B>>>();
    convert_edges<<<EB, 256>>>(ei_raw);   // also counts degrees
    scan1<<<NBLK, SCAN_B>>>();
    scan2<<<1, SCAN_B>>>();
    scan3<<<NBLK, SCAN_B>>>();
    edge_fill_csr<<<EB, 256>>>();

    dim3 ggrid(2, (NN + 127) / 128);

    // node_proj -> xcat[:, :256]
    gemm_tf32<<<ggrid, 256>>>(node_feats, NODE_IN, Wnp, bnp, xcat, 512, NN, NODE_IN);
    // edge mean + edge_proj -> xcat[:, 256:512]
    edgeproj_kernel<<<(NN + 15) / 16, 256>>>(edge_attr, Wep, bep);

    // ---- GAT layer 1 ----
    gemm_tf32<<<ggrid, 256>>>(xcat, 512, Wg1, nullptr, xh, 256, NN, 512);
    attn_dots<<<NN, 128>>>(as1, ad1);
    gat_aggregate<<<NN, 128>>>(bg1, hbuf);

    // ---- GAT layer 2 ----
    gemm_tf32<<<ggrid, 256>>>(hbuf, 256, Wg2, nullptr, xh, 256, NN, 256);
    attn_dots<<<NN, 128>>>(as2, ad2);
    gat_aggregate<<<NN, 128>>>(bg2, hbuf);

    // ---- out_proj -> d_out ----
    gemm_tf32<<<ggrid, 256>>>(hbuf, 256, Wo, bo, out, 256, NN, 256);
}